// round 5
// baseline (speedup 1.0000x reference)
#include <cuda_runtime.h>
#include <math.h>

// Problem constants
#define Gc 12
#define Hc 8
#define CIN 64
#define CQK 32
#define CVAL 32
#define COUT 64
#define Bc 2
#define Nc 512
#define NHEAD 96            // G*H
#define TOK 1024            // B*N
#define KQKV 768            // G*C_IN
#define NQKV 9216           // 3 * G*H*C_QK
#define KOUT 3072           // G*H*C_VAL
#define NOUT 768            // G*C_OUT

// Scratch (allocation-free rule: __device__ globals)
__device__ float g_q[Bc * NHEAD * Nc * CQK];     // [b][head][n][d]
__device__ float g_k[Bc * NHEAD * Nc * CQK];
__device__ float g_v[Bc * NHEAD * Nc * CVAL];
__device__ float g_att[TOK * KOUT];              // [b][n][g*256 + h*32 + d]

// ---------------------------------------------------------------------------
// Kernel 1: fused QKV projection.
//   out[tok, J] with J = p*3072 + h_out*256 + o   (p: 0=q,1=k,2=v)
//   = sum_{g,i} feat[tok, g*64+i] * Wp[(g - h_out) mod 12, o, i]
// Tiled SGEMM: BM=64, BN=64, BK=32, 256 threads, 4x4 microtile.
// ---------------------------------------------------------------------------
__global__ __launch_bounds__(256) void qkv_gemm(
    const float* __restrict__ A,
    const float* __restrict__ Wq,
    const float* __restrict__ Wk,
    const float* __restrict__ Wv)
{
    __shared__ float As[32][68];
    __shared__ float Bs[32][68];

    const int m0 = blockIdx.y * 64;
    const int J0 = blockIdx.x * 64;
    const int p     = J0 / 3072;           // constant per block
    const int rem   = J0 % 3072;
    const int h_out = rem / 256;           // constant per block
    const int o0    = rem % 256;           // multiple of 64
    const float* W = (p == 0) ? Wq : ((p == 1) ? Wk : Wv);

    const int tid = threadIdx.x;
    const int tx = tid & 15, ty = tid >> 4;
    const int rowA = tid >> 3, c4 = tid & 7;
    const int kq = tid & 31, nq = tid >> 5;

    float acc[4][4] = {};

    for (int k0 = 0; k0 < KQKV; k0 += 32) {
        // global loads for this tile
        float4 a0 = *(const float4*)(A + (size_t)(m0 + rowA) * KQKV + k0 + c4 * 4);
        float4 a1 = *(const float4*)(A + (size_t)(m0 + rowA + 32) * KQKV + k0 + c4 * 4);

        const int kg = k0 + kq;
        const int g = kg >> 6;             // same for all threads in tile
        const int i = kg & 63;
        int gg = g - h_out; if (gg < 0) gg += 12;
        const float* wb = W + gg * 16384 + i;   // + o*64
        float bvals[8];
        #pragma unroll
        for (int jj = 0; jj < 8; jj++)
            bvals[jj] = wb[(o0 + nq * 8 + jj) * 64];

        __syncthreads();
        As[c4 * 4 + 0][rowA]      = a0.x;
        As[c4 * 4 + 1][rowA]      = a0.y;
        As[c4 * 4 + 2][rowA]      = a0.z;
        As[c4 * 4 + 3][rowA]      = a0.w;
        As[c4 * 4 + 0][rowA + 32] = a1.x;
        As[c4 * 4 + 1][rowA + 32] = a1.y;
        As[c4 * 4 + 2][rowA + 32] = a1.z;
        As[c4 * 4 + 3][rowA + 32] = a1.w;
        #pragma unroll
        for (int jj = 0; jj < 8; jj++)
            Bs[kq][nq * 8 + jj] = bvals[jj];
        __syncthreads();

        #pragma unroll
        for (int kk = 0; kk < 32; kk++) {
            float4 av = *(const float4*)&As[kk][ty * 4];
            float4 bv = *(const float4*)&Bs[kk][tx * 4];
            acc[0][0] += av.x * bv.x; acc[0][1] += av.x * bv.y;
            acc[0][2] += av.x * bv.z; acc[0][3] += av.x * bv.w;
            acc[1][0] += av.y * bv.x; acc[1][1] += av.y * bv.y;
            acc[1][2] += av.y * bv.z; acc[1][3] += av.y * bv.w;
            acc[2][0] += av.z * bv.x; acc[2][1] += av.z * bv.y;
            acc[2][2] += av.z * bv.z; acc[2][3] += av.z * bv.w;
            acc[3][0] += av.w * bv.x; acc[3][1] += av.w * bv.y;
            acc[3][2] += av.w * bv.z; acc[3][3] += av.w * bv.w;
        }
    }

    float* dst = (p == 0) ? g_q : ((p == 1) ? g_k : g_v);
    #pragma unroll
    for (int mi = 0; mi < 4; mi++) {
        const int m = m0 + ty * 4 + mi;
        const int b = m >> 9, n = m & 511;
        #pragma unroll
        for (int ni = 0; ni < 4; ni++) {
            const int o = o0 + tx * 4 + ni;
            const int head = h_out * 8 + (o >> 5);
            const int d = o & 31;
            dst[(((size_t)b * 96 + head) * 512 + n) * 32 + d] = acc[mi][ni];
        }
    }
}

// ---------------------------------------------------------------------------
// Kernel 2: RMS-norm + (sequence rope + platonic rope) folded into one
// rotation per pair. 1 block = 1 token, 192 threads: thread = (head, half).
// ---------------------------------------------------------------------------
__global__ __launch_bounds__(192) void norm_rope(
    const float* __restrict__ coords,
    const int*   __restrict__ seq,
    const float* __restrict__ qw,
    const float* __restrict__ kw,
    const float* __restrict__ freqs)   // (H, 16, 3)
{
    const int t = threadIdx.x;
    const int tok = blockIdx.x;
    const int head = t >> 1, half = t & 1;
    const int g = head >> 3, h = head & 7;
    const int b = tok >> 9, n = tok & 511;

    const float pos = (float)seq[tok];
    const float cx = coords[tok * 3 + 0];
    const float cy = coords[tok * 3 + 1];
    const float cz = coords[tok * 3 + 2];

    // z-rotation by theta_g, rotated coords r = coords^T R[g]
    const float th = (float)g * 0.52359877559829887f;   // 2*pi/12
    const float cg = cosf(th), sg = sinf(th);
    const float r0 = cx * cg + cy * sg;
    const float r1 = cy * cg - cx * sg;
    const float r2 = cz;

    float* qp = g_q + (((size_t)b * 96 + head) * 512 + n) * 32 + half * 16;
    float* kp = g_k + (((size_t)b * 96 + head) * 512 + n) * 32 + half * 16;

    float qv[16], kv[16];
    #pragma unroll
    for (int e = 0; e < 4; e++) {
        float4 a = *(const float4*)(qp + e * 4);
        qv[e * 4 + 0] = a.x; qv[e * 4 + 1] = a.y; qv[e * 4 + 2] = a.z; qv[e * 4 + 3] = a.w;
        float4 c = *(const float4*)(kp + e * 4);
        kv[e * 4 + 0] = c.x; kv[e * 4 + 1] = c.y; kv[e * 4 + 2] = c.z; kv[e * 4 + 3] = c.w;
    }

    float sq = 0.f, sk = 0.f;
    #pragma unroll
    for (int e = 0; e < 16; e++) { sq += qv[e] * qv[e]; sk += kv[e] * kv[e]; }
    sq += __shfl_xor_sync(0xffffffffu, sq, 1);
    sk += __shfl_xor_sync(0xffffffffu, sk, 1);

    const float eps = 1.1920929e-07f;
    const float rq = rsqrtf(sq * (1.0f / 32.0f) + eps);
    const float rk = rsqrtf(sk * (1.0f / 32.0f) + eps);

    #pragma unroll
    for (int jj = 0; jj < 8; jj++) {
        const int j = half * 8 + jj;
        // inv_freq = 10000^(-j/16); computed in double for angle accuracy
        const float invf = (float)exp(-(double)j * 0.57564627324851148);
        const float* F = freqs + (h * 16 + j) * 3;
        const float phase = pos * invf + r0 * F[0] + r1 * F[1] + r2 * F[2];
        float sn, cs;
        sincosf(phase, &sn, &cs);

        float x1 = qv[2 * jj]     * rq * qw[2 * j];
        float x2 = qv[2 * jj + 1] * rq * qw[2 * j + 1];
        qv[2 * jj]     = x1 * cs - x2 * sn;
        qv[2 * jj + 1] = x1 * sn + x2 * cs;

        float y1 = kv[2 * jj]     * rk * kw[2 * j];
        float y2 = kv[2 * jj + 1] * rk * kw[2 * j + 1];
        kv[2 * jj]     = y1 * cs - y2 * sn;
        kv[2 * jj + 1] = y1 * sn + y2 * cs;
    }

    #pragma unroll
    for (int e = 0; e < 4; e++) {
        *(float4*)(qp + e * 4) = make_float4(qv[e*4+0], qv[e*4+1], qv[e*4+2], qv[e*4+3]);
        *(float4*)(kp + e * 4) = make_float4(kv[e*4+0], kv[e*4+1], kv[e*4+2], kv[e*4+3]);
    }
}

// ---------------------------------------------------------------------------
// Kernel 3: attention. grid (4 qblocks, 192 bh). 128 threads; one thread
// owns one q row. rms_norm bounds |score| <= sqrt(32), so exp(s) without max
// subtraction is exact softmax and fp32-safe.
// ---------------------------------------------------------------------------
__global__ __launch_bounds__(128) void attn_kernel()
{
    __shared__ __align__(16) float ks[64 * 32];
    __shared__ __align__(16) float vs[64 * 32];

    const int bh = blockIdx.y;                  // b*96 + head
    const int row = blockIdx.x * 128 + threadIdx.x;   // n
    const float scale = 0.17677669529663687f;   // 1/sqrt(32)

    const float* qrow = g_q + ((size_t)bh * 512 + row) * 32;
    float qr[32];
    #pragma unroll
    for (int e = 0; e < 8; e++) {
        float4 a = *(const float4*)(qrow + e * 4);
        qr[e*4+0] = a.x * scale; qr[e*4+1] = a.y * scale;
        qr[e*4+2] = a.z * scale; qr[e*4+3] = a.w * scale;
    }

    float acc[32] = {};
    float l = 0.f;

    for (int kb = 0; kb < 8; kb++) {
        const float4* kbase = (const float4*)(g_k + ((size_t)bh * 512 + kb * 64) * 32);
        const float4* vbase = (const float4*)(g_v + ((size_t)bh * 512 + kb * 64) * 32);
        #pragma unroll
        for (int r = 0; r < 4; r++) {
            const int idx = r * 128 + threadIdx.x;
            ((float4*)ks)[idx] = kbase[idx];
            ((float4*)vs)[idx] = vbase[idx];
        }
        __syncthreads();

        #pragma unroll 2
        for (int kk = 0; kk < 64; kk++) {
            const float4* kr = (const float4*)(ks + kk * 32);
            float s0 = 0.f, s1 = 0.f, s2 = 0.f, s3 = 0.f;
            #pragma unroll
            for (int e = 0; e < 8; e += 4) {
                float4 k0_ = kr[e + 0], k1_ = kr[e + 1], k2_ = kr[e + 2], k3_ = kr[e + 3];
                s0 += qr[(e+0)*4+0]*k0_.x + qr[(e+0)*4+1]*k0_.y + qr[(e+0)*4+2]*k0_.z + qr[(e+0)*4+3]*k0_.w;
                s1 += qr[(e+1)*4+0]*k1_.x + qr[(e+1)*4+1]*k1_.y + qr[(e+1)*4+2]*k1_.z + qr[(e+1)*4+3]*k1_.w;
                s2 += qr[(e+2)*4+0]*k2_.x + qr[(e+2)*4+1]*k2_.y + qr[(e+2)*4+2]*k2_.z + qr[(e+2)*4+3]*k2_.w;
                s3 += qr[(e+3)*4+0]*k3_.x + qr[(e+3)*4+1]*k3_.y + qr[(e+3)*4+2]*k3_.z + qr[(e+3)*4+3]*k3_.w;
            }
            const float p = __expf((s0 + s1) + (s2 + s3));
            l += p;
            const float4* vr = (const float4*)(vs + kk * 32);
            #pragma unroll
            for (int e = 0; e < 8; e++) {
                float4 vv = vr[e];
                acc[e*4+0] += p * vv.x;
                acc[e*4+1] += p * vv.y;
                acc[e*4+2] += p * vv.z;
                acc[e*4+3] += p * vv.w;
            }
        }
        __syncthreads();
    }

    const float inv = 1.0f / l;
    const int b = bh / 96, head = bh % 96;
    float* outp = g_att + ((size_t)(b * 512 + row)) * 3072 + head * 32;
    #pragma unroll
    for (int e = 0; e < 8; e++) {
        *(float4*)(outp + e * 4) =
            make_float4(acc[e*4+0] * inv, acc[e*4+1] * inv, acc[e*4+2] * inv, acc[e*4+3] * inv);
    }
}

// ---------------------------------------------------------------------------
// Kernel 4: output projection.
//   out[tok, g_out*64 + o] = sum_{g,i} att[tok, g*256+i] * Wo[(g-g_out)%12, o, i]
// ---------------------------------------------------------------------------
__global__ __launch_bounds__(256) void out_gemm(
    const float* __restrict__ Wo,
    float* __restrict__ out)
{
    __shared__ float As[32][68];
    __shared__ float Bs[32][68];

    const int m0 = blockIdx.y * 64;
    const int g_out = blockIdx.x;      // 0..11, N tile = one g_out block of 64 cols

    const int tid = threadIdx.x;
    const int tx = tid & 15, ty = tid >> 4;
    const int rowA = tid >> 3, c4 = tid & 7;
    const int kq = tid & 31, nq = tid >> 5;

    const float* A = g_att;
    float acc[4][4] = {};

    for (int k0 = 0; k0 < KOUT; k0 += 32) {
        float4 a0 = *(const float4*)(A + (size_t)(m0 + rowA) * KOUT + k0 + c4 * 4);
        float4 a1 = *(const float4*)(A + (size_t)(m0 + rowA + 32) * KOUT + k0 + c4 * 4);

        const int kg = k0 + kq;
        const int g = kg >> 8;
        const int i = kg & 255;
        int gg = g - g_out; if (gg < 0) gg += 12;
        const float* wb = Wo + gg * 16384 + i;   // + o*256
        float bvals[8];
        #pragma unroll
        for (int jj = 0; jj < 8; jj++)
            bvals[jj] = wb[(nq * 8 + jj) * 256];

        __syncthreads();
        As[c4 * 4 + 0][rowA]      = a0.x;
        As[c4 * 4 + 1][rowA]      = a0.y;
        As[c4 * 4 + 2][rowA]      = a0.z;
        As[c4 * 4 + 3][rowA]      = a0.w;
        As[c4 * 4 + 0][rowA + 32] = a1.x;
        As[c4 * 4 + 1][rowA + 32] = a1.y;
        As[c4 * 4 + 2][rowA + 32] = a1.z;
        As[c4 * 4 + 3][rowA + 32] = a1.w;
        #pragma unroll
        for (int jj = 0; jj < 8; jj++)
            Bs[kq][nq * 8 + jj] = bvals[jj];
        __syncthreads();

        #pragma unroll
        for (int kk = 0; kk < 32; kk++) {
            float4 av = *(const float4*)&As[kk][ty * 4];
            float4 bv = *(const float4*)&Bs[kk][tx * 4];
            acc[0][0] += av.x * bv.x; acc[0][1] += av.x * bv.y;
            acc[0][2] += av.x * bv.z; acc[0][3] += av.x * bv.w;
            acc[1][0] += av.y * bv.x; acc[1][1] += av.y * bv.y;
            acc[1][2] += av.y * bv.z; acc[1][3] += av.y * bv.w;
            acc[2][0] += av.z * bv.x; acc[2][1] += av.z * bv.y;
            acc[2][2] += av.z * bv.z; acc[2][3] += av.z * bv.w;
            acc[3][0] += av.w * bv.x; acc[3][1] += av.w * bv.y;
            acc[3][2] += av.w * bv.z; acc[3][3] += av.w * bv.w;
        }
    }

    #pragma unroll
    for (int mi = 0; mi < 4; mi++) {
        const int m = m0 + ty * 4 + mi;
        *(float4*)(out + (size_t)m * NOUT + g_out * 64 + tx * 4) =
            make_float4(acc[mi][0], acc[mi][1], acc[mi][2], acc[mi][3]);
    }
}

// ---------------------------------------------------------------------------
extern "C" void kernel_launch(void* const* d_in, const int* in_sizes, int n_in,
                              void* d_out, int out_size)
{
    (void)in_sizes; (void)n_in; (void)out_size;
    const float* feat   = (const float*)d_in[0];
    const float* coords = (const float*)d_in[1];
    const float* Wq     = (const float*)d_in[2];
    const float* Wk     = (const float*)d_in[3];
    const float* Wv     = (const float*)d_in[4];
    const float* Wo     = (const float*)d_in[5];
    const float* qw     = (const float*)d_in[6];
    const float* kw     = (const float*)d_in[7];
    const float* freqs  = (const float*)d_in[8];
    const int*   seq    = (const int*)d_in[9];
    float* out = (float*)d_out;

    qkv_gemm<<<dim3(NQKV / 64, TOK / 64), 256>>>(feat, Wq, Wk, Wv);
    norm_rope<<<TOK, 192>>>(coords, seq, qw, kw, freqs);
    attn_kernel<<<dim3(4, Bc * NHEAD), 128>>>();
    out_gemm<<<dim3(NOUT / 64, TOK / 64), 256>>>(Wo, out);
}

// round 11
// speedup vs baseline: 1.4614x; 1.4614x over previous
#include <cuda_runtime.h>
#include <cuda_bf16.h>
#include <math.h>
#include <stdint.h>

// ---------------- problem constants ----------------
#define Gc 12
#define Hc 8
#define CIN 64
#define CQK 32
#define CVAL 32
#define Bc 2
#define Nc 512
#define NHEAD 96            // G*H
#define TOK 1024            // B*N
#define KQKV 768            // G*C_IN
#define NQKV 9216           // 3 * G*H*C_QK
#define KOUT 3072           // G*H*C_VAL
#define NOUT 768            // G*C_OUT

// ---------------- device scratch (allocation-free rule) ----------------
__device__ float g_q[Bc * NHEAD * Nc * CQK];     // [b][head][n][d]
__device__ float g_k[Bc * NHEAD * Nc * CQK];
__device__ float g_v[Bc * NHEAD * Nc * CVAL];
__device__ float g_att[TOK * KOUT];              // [b*n][g*256 + h*32 + d]

__device__ __nv_bfloat16 g_feat_hi[TOK * KQKV];
__device__ __nv_bfloat16 g_feat_lo[TOK * KQKV];
__device__ __nv_bfloat16 g_w_hi[3 * Gc * 256 * CIN];   // [p][g][o(256)][i(64)]
__device__ __nv_bfloat16 g_w_lo[3 * Gc * 256 * CIN];
__device__ __nv_bfloat16 g_wo_hi[Gc * 64 * 256];       // [g][o(64)][i(256)]
__device__ __nv_bfloat16 g_wo_lo[Gc * 64 * 256];
__device__ __nv_bfloat16 g_att_hi[TOK * KOUT];
__device__ __nv_bfloat16 g_att_lo[TOK * KOUT];

// ---------------- helpers (portable sm_80+ PTX only) ----------------
__device__ __forceinline__ uint32_t smem_u32(const void* p) {
    uint32_t a;
    asm("{ .reg .u64 t; cvta.to.shared.u64 t, %1; cvt.u32.u64 %0, t; }"
        : "=r"(a) : "l"(p));
    return a;
}

#define SMEM_SWIZZLE_128B(byte_offset) \
    ((byte_offset) ^ (((byte_offset) >> 3) & 0x70))

__device__ __forceinline__ void ldsm4(uint32_t* r, uint32_t addr) {
    asm volatile("ldmatrix.sync.aligned.m8n8.x4.shared.b16 {%0,%1,%2,%3}, [%4];"
        : "=r"(r[0]), "=r"(r[1]), "=r"(r[2]), "=r"(r[3]) : "r"(addr));
}

__device__ __forceinline__ void mma16816(float* c, const uint32_t* a,
                                         uint32_t b0, uint32_t b1) {
    asm volatile(
        "mma.sync.aligned.m16n8k16.row.col.f32.bf16.bf16.f32 "
        "{%0,%1,%2,%3}, {%4,%5,%6,%7}, {%8,%9}, {%0,%1,%2,%3};"
        : "+f"(c[0]), "+f"(c[1]), "+f"(c[2]), "+f"(c[3])
        : "r"(a[0]), "r"(a[1]), "r"(a[2]), "r"(a[3]), "r"(b0), "r"(b1));
}

// FFMA-only exp (avoids MUFU bottleneck). Valid for |x| <= ~40.
// 2^f Taylor deg-5 on f in [-0.5,0.5]: max rel err ~2.4e-6.
__device__ __forceinline__ float fast_exp(float x) {
    float y = x * 1.4426950408889634f;
    float t = y + 12582912.0f;                    // 2^23 + 2^22 magic
    int   n = __float_as_int(t) - 0x4B400000;     // round-to-nearest int
    float f = y - (t - 12582912.0f);
    float p = fmaf(f, 0.0013333558f, 0.0096181291f);
    p = fmaf(f, p, 0.0555041087f);
    p = fmaf(f, p, 0.2402265070f);
    p = fmaf(f, p, 0.6931471806f);
    p = fmaf(f, p, 1.0f);
    return p * __int_as_float((n + 127) << 23);
}

// smem tile offsets (bytes): 4 tiles of 128x64 bf16 (16KB) = 64KB dynamic
#define T_AH 0
#define T_AL 16384
#define T_BH 32768
#define T_BL 49152
#define MMA_SMEM_BYTES 65536

// ---------------------------------------------------------------------------
// prep: fp32 -> bf16 hi/lo splits for feat, Wq/Wk/Wv, Wo
// ---------------------------------------------------------------------------
__global__ __launch_bounds__(256) void prep_inputs(
    const float* __restrict__ feat,
    const float* __restrict__ Wq, const float* __restrict__ Wk,
    const float* __restrict__ Wv, const float* __restrict__ Wo)
{
    const int i = blockIdx.x * 256 + threadIdx.x;
    if (i < 786432) {
        float x = feat[i];
        __nv_bfloat16 h = __float2bfloat16(x);
        g_feat_hi[i] = h;
        g_feat_lo[i] = __float2bfloat16(x - __bfloat162float(h));
    } else if (i < 786432 + 589824) {
        int j = i - 786432;
        const float* W = (j < 196608) ? Wq : ((j < 393216) ? Wk : Wv);
        float x = W[j % 196608];
        __nv_bfloat16 h = __float2bfloat16(x);
        g_w_hi[j] = h;
        g_w_lo[j] = __float2bfloat16(x - __bfloat162float(h));
    } else {
        int j = i - 1376256;
        float x = Wo[j];
        __nv_bfloat16 h = __float2bfloat16(x);
        g_wo_hi[j] = h;
        g_wo_lo[j] = __float2bfloat16(x - __bfloat162float(h));
    }
}

__global__ __launch_bounds__(256) void prep_att_split()
{
    const int i = blockIdx.x * 256 + threadIdx.x;   // < 1024*3072
    float x = g_att[i];
    __nv_bfloat16 h = __float2bfloat16(x);
    g_att_hi[i] = h;
    g_att_lo[i] = __float2bfloat16(x - __bfloat162float(h));
}

// ---------------------------------------------------------------------------
// QKV projection: C[1024 x 9216] via mma.sync bf16 hi/lo (3-term).
// CTA tile 128x128, BK=64 (one circulant group g per chunk), 8 warps (4m x 2n),
// warp tile 32x64. grid (72, 8), 256 threads.
// ---------------------------------------------------------------------------
__global__ __launch_bounds__(256) void qkv_mma()
{
    extern __shared__ __align__(16) char smem[];
    const uint32_t sb = smem_u32(smem);
    const int tid = threadIdx.x, wid = tid >> 5, lane = tid & 31;
    const int wm = wid & 3, wn = wid >> 2;          // 4 x 2 warp grid
    const int m0 = blockIdx.y * 128;
    const int J0 = blockIdx.x * 128;
    const int p = J0 / 3072, rem = J0 % 3072;
    const int h_out = rem / 256, o0 = rem % 256;    // o0 in {0,128}

    const __nv_bfloat16* Whi = g_w_hi + p * 196608;
    const __nv_bfloat16* Wlo = g_w_lo + p * 196608;

    float acc[2][8][4] = {};

    // ldmatrix lane-address components (tile-local)
    const int a_r = wm * 32 + (lane & 15);          // + mt*16
    const int a_c2 = ((lane >> 4) << 3) * 2;        // + k0*2 (bytes)
    const int b_r = wn * 64 + ((lane >> 4) << 3) + (lane & 7);   // + pt*16
    const int b_c2 = (((lane >> 3) & 1) << 3) * 2;  // + k0*2 (bytes)

    for (int g = 0; g < 12; g++) {
        __syncthreads();
        const int gg0 = g - h_out;
        const int gg = (gg0 < 0) ? gg0 + 12 : gg0;

        #pragma unroll
        for (int c = 0; c < 4; c++) {
            const int chunk = tid + c * 256;        // 0..1023
            const int row = chunk >> 3, c8 = chunk & 7;
            const uint32_t sw = SMEM_SWIZZLE_128B(row * 128 + c8 * 16);
            const size_t aoff = (size_t)(m0 + row) * KQKV + g * 64 + c8 * 8;
            const size_t boff = (size_t)(gg * 256 + o0 + row) * 64 + c8 * 8;
            *(uint4*)(smem + T_AH + sw) = *(const uint4*)(g_feat_hi + aoff);
            *(uint4*)(smem + T_AL + sw) = *(const uint4*)(g_feat_lo + aoff);
            *(uint4*)(smem + T_BH + sw) = *(const uint4*)(Whi + boff);
            *(uint4*)(smem + T_BL + sw) = *(const uint4*)(Wlo + boff);
        }
        __syncthreads();

        #pragma unroll
        for (int ks = 0; ks < 4; ks++) {
            const int k0b = ks * 32;                // k0 * 2 bytes
            uint32_t ah[2][4], al[2][4], bh[4][4], bl[4][4];
            #pragma unroll
            for (int mt = 0; mt < 2; mt++) {
                const uint32_t off = SMEM_SWIZZLE_128B((a_r + mt * 16) * 128 + k0b + a_c2);
                ldsm4(ah[mt], sb + T_AH + off);
                ldsm4(al[mt], sb + T_AL + off);
            }
            #pragma unroll
            for (int pt = 0; pt < 4; pt++) {
                const uint32_t off = SMEM_SWIZZLE_128B((b_r + pt * 16) * 128 + k0b + b_c2);
                ldsm4(bh[pt], sb + T_BH + off);
                ldsm4(bl[pt], sb + T_BL + off);
            }
            #pragma unroll
            for (int mt = 0; mt < 2; mt++)
                #pragma unroll
                for (int pt = 0; pt < 4; pt++) {
                    mma16816(acc[mt][2*pt+0], ah[mt], bh[pt][0], bh[pt][1]);
                    mma16816(acc[mt][2*pt+1], ah[mt], bh[pt][2], bh[pt][3]);
                    mma16816(acc[mt][2*pt+0], ah[mt], bl[pt][0], bl[pt][1]);
                    mma16816(acc[mt][2*pt+1], ah[mt], bl[pt][2], bl[pt][3]);
                    mma16816(acc[mt][2*pt+0], al[mt], bh[pt][0], bh[pt][1]);
                    mma16816(acc[mt][2*pt+1], al[mt], bh[pt][2], bh[pt][3]);
                }
        }
    }

    // writeback: c0,c1 -> (row=lane/4, col=(lane%4)*2), c2,c3 -> row+8
    float* dstbase = (p == 0) ? g_q : ((p == 1) ? g_k : g_v);
    #pragma unroll
    for (int mt = 0; mt < 2; mt++) {
        const int r = m0 + wm * 32 + mt * 16 + (lane >> 2);
        const int b0i = r >> 9, n0i = r & 511;
        const int r2 = r + 8;
        const int b1i = r2 >> 9, n1i = r2 & 511;
        #pragma unroll
        for (int nt = 0; nt < 8; nt++) {
            const int col = wn * 64 + nt * 8 + (lane & 3) * 2;
            const int o = o0 + col;
            const int head = h_out * 8 + (o >> 5);
            const int d = o & 31;
            float* d0 = dstbase + (((size_t)b0i * 96 + head) * 512 + n0i) * 32 + d;
            float* d1 = dstbase + (((size_t)b1i * 96 + head) * 512 + n1i) * 32 + d;
            *(float2*)d0 = make_float2(acc[mt][nt][0], acc[mt][nt][1]);
            *(float2*)d1 = make_float2(acc[mt][nt][2], acc[mt][nt][3]);
        }
    }
}

// ---------------------------------------------------------------------------
// Output projection: C[1024 x 768] = att[1024 x 3072] * Wo' (circulant).
// Same structure; 48 K-chunks of 64. grid (6, 8), 256 threads.
// ---------------------------------------------------------------------------
__global__ __launch_bounds__(256) void out_mma(float* __restrict__ out)
{
    extern __shared__ __align__(16) char smem[];
    const uint32_t sb = smem_u32(smem);
    const int tid = threadIdx.x, wid = tid >> 5, lane = tid & 31;
    const int wm = wid & 3, wn = wid >> 2;
    const int m0 = blockIdx.y * 128;
    const int J0 = blockIdx.x * 128;

    float acc[2][8][4] = {};

    const int a_r = wm * 32 + (lane & 15);
    const int a_c2 = ((lane >> 4) << 3) * 2;
    const int b_r = wn * 64 + ((lane >> 4) << 3) + (lane & 7);
    const int b_c2 = (((lane >> 3) & 1) << 3) * 2;

    for (int ch = 0; ch < 48; ch++) {
        __syncthreads();
        const int gsrc = ch >> 2;
        const int i0 = (ch & 3) * 64;

        #pragma unroll
        for (int c = 0; c < 4; c++) {
            const int chunk = tid + c * 256;
            const int row = chunk >> 3, c8 = chunk & 7;
            const uint32_t sw = SMEM_SWIZZLE_128B(row * 128 + c8 * 16);
            const size_t aoff = (size_t)(m0 + row) * KOUT + ch * 64 + c8 * 8;
            const int Jrow = J0 + row;
            const int g_out = Jrow >> 6, o = Jrow & 63;
            int gg = gsrc - g_out; if (gg < 0) gg += 12;
            const size_t boff = (size_t)(gg * 64 + o) * 256 + i0 + c8 * 8;
            *(uint4*)(smem + T_AH + sw) = *(const uint4*)(g_att_hi + aoff);
            *(uint4*)(smem + T_AL + sw) = *(const uint4*)(g_att_lo + aoff);
            *(uint4*)(smem + T_BH + sw) = *(const uint4*)(g_wo_hi + boff);
            *(uint4*)(smem + T_BL + sw) = *(const uint4*)(g_wo_lo + boff);
        }
        __syncthreads();

        #pragma unroll
        for (int ks = 0; ks < 4; ks++) {
            const int k0b = ks * 32;
            uint32_t ah[2][4], al[2][4], bh[4][4], bl[4][4];
            #pragma unroll
            for (int mt = 0; mt < 2; mt++) {
                const uint32_t off = SMEM_SWIZZLE_128B((a_r + mt * 16) * 128 + k0b + a_c2);
                ldsm4(ah[mt], sb + T_AH + off);
                ldsm4(al[mt], sb + T_AL + off);
            }
            #pragma unroll
            for (int pt = 0; pt < 4; pt++) {
                const uint32_t off = SMEM_SWIZZLE_128B((b_r + pt * 16) * 128 + k0b + b_c2);
                ldsm4(bh[pt], sb + T_BH + off);
                ldsm4(bl[pt], sb + T_BL + off);
            }
            #pragma unroll
            for (int mt = 0; mt < 2; mt++)
                #pragma unroll
                for (int pt = 0; pt < 4; pt++) {
                    mma16816(acc[mt][2*pt+0], ah[mt], bh[pt][0], bh[pt][1]);
                    mma16816(acc[mt][2*pt+1], ah[mt], bh[pt][2], bh[pt][3]);
                    mma16816(acc[mt][2*pt+0], ah[mt], bl[pt][0], bl[pt][1]);
                    mma16816(acc[mt][2*pt+1], ah[mt], bl[pt][2], bl[pt][3]);
                    mma16816(acc[mt][2*pt+0], al[mt], bh[pt][0], bh[pt][1]);
                    mma16816(acc[mt][2*pt+1], al[mt], bh[pt][2], bh[pt][3]);
                }
        }
    }

    #pragma unroll
    for (int mt = 0; mt < 2; mt++) {
        const int r = m0 + wm * 32 + mt * 16 + (lane >> 2);
        #pragma unroll
        for (int nt = 0; nt < 8; nt++) {
            const int J = J0 + wn * 64 + nt * 8 + (lane & 3) * 2;
            *(float2*)(out + (size_t)r * NOUT + J) =
                make_float2(acc[mt][nt][0], acc[mt][nt][1]);
            *(float2*)(out + (size_t)(r + 8) * NOUT + J) =
                make_float2(acc[mt][nt][2], acc[mt][nt][3]);
        }
    }
}

// ---------------------------------------------------------------------------
// RMS-norm + fused (sequence + platonic) rope. 1 block = 1 token.
// ---------------------------------------------------------------------------
__global__ __launch_bounds__(192) void norm_rope(
    const float* __restrict__ coords,
    const int*   __restrict__ seq,
    const float* __restrict__ qw,
    const float* __restrict__ kw,
    const float* __restrict__ freqs)
{
    const int t = threadIdx.x;
    const int tok = blockIdx.x;
    const int head = t >> 1, half = t & 1;
    const int g = head >> 3, h = head & 7;
    const int b = tok >> 9, n = tok & 511;

    const float pos = (float)seq[tok];
    const float cx = coords[tok * 3 + 0];
    const float cy = coords[tok * 3 + 1];
    const float cz = coords[tok * 3 + 2];

    const float th = (float)g * 0.52359877559829887f;
    const float cg = cosf(th), sg = sinf(th);
    const float r0 = cx * cg + cy * sg;
    const float r1 = cy * cg - cx * sg;
    const float r2 = cz;

    float* qp = g_q + (((size_t)b * 96 + head) * 512 + n) * 32 + half * 16;
    float* kp = g_k + (((size_t)b * 96 + head) * 512 + n) * 32 + half * 16;

    float qv[16], kv[16];
    #pragma unroll
    for (int e = 0; e < 4; e++) {
        float4 a = *(const float4*)(qp + e * 4);
        qv[e*4+0] = a.x; qv[e*4+1] = a.y; qv[e*4+2] = a.z; qv[e*4+3] = a.w;
        float4 c = *(const float4*)(kp + e * 4);
        kv[e*4+0] = c.x; kv[e*4+1] = c.y; kv[e*4+2] = c.z; kv[e*4+3] = c.w;
    }

    float sq = 0.f, sk = 0.f;
    #pragma unroll
    for (int e = 0; e < 16; e++) { sq += qv[e] * qv[e]; sk += kv[e] * kv[e]; }
    sq += __shfl_xor_sync(0xffffffffu, sq, 1);
    sk += __shfl_xor_sync(0xffffffffu, sk, 1);

    const float eps = 1.1920929e-07f;
    const float rq = rsqrtf(sq * (1.0f / 32.0f) + eps);
    const float rk = rsqrtf(sk * (1.0f / 32.0f) + eps);

    #pragma unroll
    for (int jj = 0; jj < 8; jj++) {
        const int j = half * 8 + jj;
        const float invf = (float)exp(-(double)j * 0.57564627324851148);
        const float* F = freqs + (h * 16 + j) * 3;
        const float phase = pos * invf + r0 * F[0] + r1 * F[1] + r2 * F[2];
        float sn, cs;
        sincosf(phase, &sn, &cs);

        float x1 = qv[2*jj]   * rq * qw[2*j];
        float x2 = qv[2*jj+1] * rq * qw[2*j+1];
        qv[2*jj]   = x1 * cs - x2 * sn;
        qv[2*jj+1] = x1 * sn + x2 * cs;

        float y1 = kv[2*jj]   * rk * kw[2*j];
        float y2 = kv[2*jj+1] * rk * kw[2*j+1];
        kv[2*jj]   = y1 * cs - y2 * sn;
        kv[2*jj+1] = y1 * sn + y2 * cs;
    }

    #pragma unroll
    for (int e = 0; e < 4; e++) {
        *(float4*)(qp + e * 4) = make_float4(qv[e*4+0], qv[e*4+1], qv[e*4+2], qv[e*4+3]);
        *(float4*)(kp + e * 4) = make_float4(kv[e*4+0], kv[e*4+1], kv[e*4+2], kv[e*4+3]);
    }
}

// ---------------------------------------------------------------------------
// Attention (fp32; |score| <= sqrt(32): exp without max is exact softmax).
// fast_exp keeps exp off the MUFU pipe (was the bottleneck).
// ---------------------------------------------------------------------------
__global__ __launch_bounds__(128) void attn_kernel()
{
    __shared__ __align__(16) float ks[64 * 32];
    __shared__ __align__(16) float vs[64 * 32];

    const int bh = blockIdx.y;
    const int row = blockIdx.x * 128 + threadIdx.x;
    const float scale = 0.17677669529663687f;

    const float* qrow = g_q + ((size_t)bh * 512 + row) * 32;
    float qr[32];
    #pragma unroll
    for (int e = 0; e < 8; e++) {
        float4 a = *(const float4*)(qrow + e * 4);
        qr[e*4+0] = a.x * scale; qr[e*4+1] = a.y * scale;
        qr[e*4+2] = a.z * scale; qr[e*4+3] = a.w * scale;
    }

    float acc[32] = {};
    float l = 0.f;

    for (int kb = 0; kb < 8; kb++) {
        const float4* kbase = (const float4*)(g_k + ((size_t)bh * 512 + kb * 64) * 32);
        const float4* vbase = (const float4*)(g_v + ((size_t)bh * 512 + kb * 64) * 32);
        #pragma unroll
        for (int r = 0; r < 4; r++) {
            const int idx = r * 128 + threadIdx.x;
            ((float4*)ks)[idx] = kbase[idx];
            ((float4*)vs)[idx] = vbase[idx];
        }
        __syncthreads();

        #pragma unroll 2
        for (int kk = 0; kk < 64; kk++) {
            const float4* kr = (const float4*)(ks + kk * 32);
            float s0 = 0.f, s1 = 0.f, s2 = 0.f, s3 = 0.f;
            #pragma unroll
            for (int e = 0; e < 8; e += 4) {
                float4 k0_ = kr[e+0], k1_ = kr[e+1], k2_ = kr[e+2], k3_ = kr[e+3];
                s0 += qr[(e+0)*4+0]*k0_.x + qr[(e+0)*4+1]*k0_.y + qr[(e+0)*4+2]*k0_.z + qr[(e+0)*4+3]*k0_.w;
                s1 += qr[(e+1)*4+0]*k1_.x + qr[(e+1)*4+1]*k1_.y + qr[(e+1)*4+2]*k1_.z + qr[(e+1)*4+3]*k1_.w;
                s2 += qr[(e+2)*4+0]*k2_.x + qr[(e+2)*4+1]*k2_.y + qr[(e+2)*4+2]*k2_.z + qr[(e+2)*4+3]*k2_.w;
                s3 += qr[(e+3)*4+0]*k3_.x + qr[(e+3)*4+1]*k3_.y + qr[(e+3)*4+2]*k3_.z + qr[(e+3)*4+3]*k3_.w;
            }
            const float p = fast_exp((s0 + s1) + (s2 + s3));
            l += p;
            const float4* vr = (const float4*)(vs + kk * 32);
            #pragma unroll
            for (int e = 0; e < 8; e++) {
                float4 vv = vr[e];
                acc[e*4+0] += p * vv.x;
                acc[e*4+1] += p * vv.y;
                acc[e*4+2] += p * vv.z;
                acc[e*4+3] += p * vv.w;
            }
        }
        __syncthreads();
    }

    const float inv = 1.0f / l;
    const int b = bh / 96, head = bh % 96;
    float* outp = g_att + ((size_t)(b * 512 + row)) * 3072 + head * 32;
    #pragma unroll
    for (int e = 0; e < 8; e++) {
        *(float4*)(outp + e * 4) =
            make_float4(acc[e*4+0]*inv, acc[e*4+1]*inv, acc[e*4+2]*inv, acc[e*4+3]*inv);
    }
}

// ---------------------------------------------------------------------------
extern "C" void kernel_launch(void* const* d_in, const int* in_sizes, int n_in,
                              void* d_out, int out_size)
{
    (void)in_sizes; (void)n_in; (void)out_size;
    const float* feat   = (const float*)d_in[0];
    const float* coords = (const float*)d_in[1];
    const float* Wq     = (const float*)d_in[2];
    const float* Wk     = (const float*)d_in[3];
    const float* Wv     = (const float*)d_in[4];
    const float* Wo     = (const float*)d_in[5];
    const float* qw     = (const float*)d_in[6];
    const float* kw     = (const float*)d_in[7];
    const float* freqs  = (const float*)d_in[8];
    const int*   seq    = (const int*)d_in[9];
    float* out = (float*)d_out;

    cudaFuncSetAttribute(qkv_mma, cudaFuncAttributeMaxDynamicSharedMemorySize, MMA_SMEM_BYTES);
    cudaFuncSetAttribute(out_mma, cudaFuncAttributeMaxDynamicSharedMemorySize, MMA_SMEM_BYTES);

    prep_inputs<<<6144, 256>>>(feat, Wq, Wk, Wv, Wo);          // 1572864 elems
    qkv_mma<<<dim3(72, 8), 256, MMA_SMEM_BYTES>>>();
    norm_rope<<<TOK, 192>>>(coords, seq, qw, kw, freqs);
    attn_kernel<<<dim3(4, Bc * NHEAD), 128>>>();
    prep_att_split<<<12288, 256>>>();                          // 3145728 elems
    out_mma<<<dim3(6, 8), 256, MMA_SMEM_BYTES>>>(out);
}

// round 12
// speedup vs baseline: 2.0657x; 1.4135x over previous
#include <cuda_runtime.h>
#include <cuda_bf16.h>
#include <math.h>
#include <stdint.h>

// ---------------- problem constants ----------------
#define Gc 12
#define Hc 8
#define CIN 64
#define CQK 32
#define CVAL 32
#define Bc 2
#define Nc 512
#define NHEAD 96            // G*H
#define TOK 1024            // B*N
#define KQKV 768            // G*C_IN
#define NQKV 9216           // 3 * G*H*C_QK
#define KOUT 3072           // G*H*C_VAL
#define NOUT 768            // G*C_OUT

// ---------------- device scratch (allocation-free rule) ----------------
__device__ float g_q[Bc * NHEAD * Nc * CQK];     // fp32 q before norm/rope
__device__ float g_k[Bc * NHEAD * Nc * CQK];

// bf16 hi/lo operands for tensor-core stages; layout [bh][n][d]
__device__ __nv_bfloat16 g_qh[Bc * NHEAD * Nc * CQK];
__device__ __nv_bfloat16 g_ql[Bc * NHEAD * Nc * CQK];
__device__ __nv_bfloat16 g_kh[Bc * NHEAD * Nc * CQK];
__device__ __nv_bfloat16 g_kl[Bc * NHEAD * Nc * CQK];
__device__ __nv_bfloat16 g_vh[Bc * NHEAD * Nc * CVAL];
__device__ __nv_bfloat16 g_vl[Bc * NHEAD * Nc * CVAL];

__device__ __nv_bfloat16 g_feat_hi[TOK * KQKV];
__device__ __nv_bfloat16 g_feat_lo[TOK * KQKV];
__device__ __nv_bfloat16 g_w_hi[3 * Gc * 256 * CIN];   // [p][g][o(256)][i(64)]
__device__ __nv_bfloat16 g_w_lo[3 * Gc * 256 * CIN];
__device__ __nv_bfloat16 g_wo_hi[Gc * 64 * 256];       // [g][o(64)][i(256)]
__device__ __nv_bfloat16 g_wo_lo[Gc * 64 * 256];
__device__ __nv_bfloat16 g_att_hi[TOK * KOUT];         // [tok][g*256+h*32+d]
__device__ __nv_bfloat16 g_att_lo[TOK * KOUT];

// ---------------- helpers (portable sm_80+ PTX only) ----------------
__device__ __forceinline__ uint32_t smem_u32(const void* p) {
    uint32_t a;
    asm("{ .reg .u64 t; cvta.to.shared.u64 t, %1; cvt.u32.u64 %0, t; }"
        : "=r"(a) : "l"(p));
    return a;
}

#define SMEM_SWIZZLE_128B(byte_offset) \
    ((byte_offset) ^ (((byte_offset) >> 3) & 0x70))

__device__ __forceinline__ void ldsm4(uint32_t* r, uint32_t addr) {
    asm volatile("ldmatrix.sync.aligned.m8n8.x4.shared.b16 {%0,%1,%2,%3}, [%4];"
        : "=r"(r[0]), "=r"(r[1]), "=r"(r[2]), "=r"(r[3]) : "r"(addr));
}
__device__ __forceinline__ void ldsm4t(uint32_t* r, uint32_t addr) {
    asm volatile("ldmatrix.sync.aligned.m8n8.x4.trans.shared.b16 {%0,%1,%2,%3}, [%4];"
        : "=r"(r[0]), "=r"(r[1]), "=r"(r[2]), "=r"(r[3]) : "r"(addr));
}

__device__ __forceinline__ void mma16816(float* c, const uint32_t* a,
                                         uint32_t b0, uint32_t b1) {
    asm volatile(
        "mma.sync.aligned.m16n8k16.row.col.f32.bf16.bf16.f32 "
        "{%0,%1,%2,%3}, {%4,%5,%6,%7}, {%8,%9}, {%0,%1,%2,%3};"
        : "+f"(c[0]), "+f"(c[1]), "+f"(c[2]), "+f"(c[3])
        : "r"(a[0]), "r"(a[1]), "r"(a[2]), "r"(a[3]), "r"(b0), "r"(b1));
}

// pack two fp32 into bf16x2: element0 -> low half (first PTX src is HIGH half)
__device__ __forceinline__ uint32_t packbf(float e0, float e1) {
    uint32_t d;
    asm("cvt.rn.bf16x2.f32 %0, %1, %2;" : "=r"(d) : "f"(e1), "f"(e0));
    return d;
}
// residual (lo) pack given the hi pack
__device__ __forceinline__ uint32_t packlo(float s0, float s1, uint32_t h) {
    float h0 = __uint_as_float(h << 16);
    float h1 = __uint_as_float(h & 0xFFFF0000u);
    return packbf(s0 - h0, s1 - h1);
}

// FFMA-only exp (no MUFU). Valid for |x| <= ~40, rel err ~2.4e-6.
__device__ __forceinline__ float fast_exp(float x) {
    float y = x * 1.4426950408889634f;
    float t = y + 12582912.0f;                    // 2^23 + 2^22 magic
    int   n = __float_as_int(t) - 0x4B400000;
    float f = y - (t - 12582912.0f);
    float p = fmaf(f, 0.0013333558f, 0.0096181291f);
    p = fmaf(f, p, 0.0555041087f);
    p = fmaf(f, p, 0.2402265070f);
    p = fmaf(f, p, 0.6931471806f);
    p = fmaf(f, p, 1.0f);
    return p * __int_as_float((n + 127) << 23);
}

// GEMM smem tile offsets: 4 tiles of 128x64 bf16 (16KB) = 64KB dynamic
#define T_AH 0
#define T_AL 16384
#define T_BH 32768
#define T_BL 49152
#define MMA_SMEM_BYTES 65536

// ---------------------------------------------------------------------------
// prep: fp32 -> bf16 hi/lo splits for feat, Wq/Wk/Wv, Wo
// ---------------------------------------------------------------------------
__global__ __launch_bounds__(256) void prep_inputs(
    const float* __restrict__ feat,
    const float* __restrict__ Wq, const float* __restrict__ Wk,
    const float* __restrict__ Wv, const float* __restrict__ Wo)
{
    const int i = blockIdx.x * 256 + threadIdx.x;
    if (i < 786432) {
        float x = feat[i];
        __nv_bfloat16 h = __float2bfloat16(x);
        g_feat_hi[i] = h;
        g_feat_lo[i] = __float2bfloat16(x - __bfloat162float(h));
    } else if (i < 786432 + 589824) {
        int j = i - 786432;
        const float* W = (j < 196608) ? Wq : ((j < 393216) ? Wk : Wv);
        float x = W[j % 196608];
        __nv_bfloat16 h = __float2bfloat16(x);
        g_w_hi[j] = h;
        g_w_lo[j] = __float2bfloat16(x - __bfloat162float(h));
    } else {
        int j = i - 1376256;
        float x = Wo[j];
        __nv_bfloat16 h = __float2bfloat16(x);
        g_wo_hi[j] = h;
        g_wo_lo[j] = __float2bfloat16(x - __bfloat162float(h));
    }
}

// ---------------------------------------------------------------------------
// QKV projection: C[1024 x 9216] via mma.sync bf16 hi/lo (3-term).
// q,k written fp32 (norm/rope follows); v written bf16 hi/lo directly.
// ---------------------------------------------------------------------------
__global__ __launch_bounds__(256) void qkv_mma()
{
    extern __shared__ __align__(16) char smem[];
    const uint32_t sb = smem_u32(smem);
    const int tid = threadIdx.x, wid = tid >> 5, lane = tid & 31;
    const int wm = wid & 3, wn = wid >> 2;          // 4 x 2 warp grid
    const int m0 = blockIdx.y * 128;
    const int J0 = blockIdx.x * 128;
    const int p = J0 / 3072, rem = J0 % 3072;
    const int h_out = rem / 256, o0 = rem % 256;    // o0 in {0,128}

    const __nv_bfloat16* Whi = g_w_hi + p * 196608;
    const __nv_bfloat16* Wlo = g_w_lo + p * 196608;

    float acc[2][8][4] = {};

    const int a_r = wm * 32 + (lane & 15);
    const int a_c2 = ((lane >> 4) << 3) * 2;
    const int b_r = wn * 64 + ((lane >> 4) << 3) + (lane & 7);
    const int b_c2 = (((lane >> 3) & 1) << 3) * 2;

    for (int g = 0; g < 12; g++) {
        __syncthreads();
        const int gg0 = g - h_out;
        const int gg = (gg0 < 0) ? gg0 + 12 : gg0;

        #pragma unroll
        for (int c = 0; c < 4; c++) {
            const int chunk = tid + c * 256;        // 0..1023
            const int row = chunk >> 3, c8 = chunk & 7;
            const uint32_t sw = SMEM_SWIZZLE_128B(row * 128 + c8 * 16);
            const size_t aoff = (size_t)(m0 + row) * KQKV + g * 64 + c8 * 8;
            const size_t boff = (size_t)(gg * 256 + o0 + row) * 64 + c8 * 8;
            *(uint4*)(smem + T_AH + sw) = *(const uint4*)(g_feat_hi + aoff);
            *(uint4*)(smem + T_AL + sw) = *(const uint4*)(g_feat_lo + aoff);
            *(uint4*)(smem + T_BH + sw) = *(const uint4*)(Whi + boff);
            *(uint4*)(smem + T_BL + sw) = *(const uint4*)(Wlo + boff);
        }
        __syncthreads();

        #pragma unroll
        for (int ks = 0; ks < 4; ks++) {
            const int k0b = ks * 32;
            uint32_t ah[2][4], al[2][4], bh[4][4], bl[4][4];
            #pragma unroll
            for (int mt = 0; mt < 2; mt++) {
                const uint32_t off = SMEM_SWIZZLE_128B((a_r + mt * 16) * 128 + k0b + a_c2);
                ldsm4(ah[mt], sb + T_AH + off);
                ldsm4(al[mt], sb + T_AL + off);
            }
            #pragma unroll
            for (int pt = 0; pt < 4; pt++) {
                const uint32_t off = SMEM_SWIZZLE_128B((b_r + pt * 16) * 128 + k0b + b_c2);
                ldsm4(bh[pt], sb + T_BH + off);
                ldsm4(bl[pt], sb + T_BL + off);
            }
            #pragma unroll
            for (int mt = 0; mt < 2; mt++)
                #pragma unroll
                for (int pt = 0; pt < 4; pt++) {
                    mma16816(acc[mt][2*pt+0], ah[mt], bh[pt][0], bh[pt][1]);
                    mma16816(acc[mt][2*pt+1], ah[mt], bh[pt][2], bh[pt][3]);
                    mma16816(acc[mt][2*pt+0], ah[mt], bl[pt][0], bl[pt][1]);
                    mma16816(acc[mt][2*pt+1], ah[mt], bl[pt][2], bl[pt][3]);
                    mma16816(acc[mt][2*pt+0], al[mt], bh[pt][0], bh[pt][1]);
                    mma16816(acc[mt][2*pt+1], al[mt], bh[pt][2], bh[pt][3]);
                }
        }
    }

    #pragma unroll
    for (int mt = 0; mt < 2; mt++) {
        const int r = m0 + wm * 32 + mt * 16 + (lane >> 2);
        const int b0i = r >> 9, n0i = r & 511;
        const int r2 = r + 8;
        const int b1i = r2 >> 9, n1i = r2 & 511;
        #pragma unroll
        for (int nt = 0; nt < 8; nt++) {
            const int col = wn * 64 + nt * 8 + (lane & 3) * 2;
            const int o = o0 + col;
            const int head = h_out * 8 + (o >> 5);
            const int d = o & 31;
            const size_t a0 = (((size_t)b0i * 96 + head) * 512 + n0i) * 32 + d;
            const size_t a1 = (((size_t)b1i * 96 + head) * 512 + n1i) * 32 + d;
            if (p == 2) {
                uint32_t h0 = packbf(acc[mt][nt][0], acc[mt][nt][1]);
                *(uint32_t*)&g_vh[a0] = h0;
                *(uint32_t*)&g_vl[a0] = packlo(acc[mt][nt][0], acc[mt][nt][1], h0);
                uint32_t h1 = packbf(acc[mt][nt][2], acc[mt][nt][3]);
                *(uint32_t*)&g_vh[a1] = h1;
                *(uint32_t*)&g_vl[a1] = packlo(acc[mt][nt][2], acc[mt][nt][3], h1);
            } else {
                float* dstbase = (p == 0) ? g_q : g_k;
                *(float2*)(dstbase + a0) = make_float2(acc[mt][nt][0], acc[mt][nt][1]);
                *(float2*)(dstbase + a1) = make_float2(acc[mt][nt][2], acc[mt][nt][3]);
            }
        }
    }
}

// ---------------------------------------------------------------------------
// RMS-norm + fused (sequence + platonic) rope; emits q,k as bf16 hi/lo
// with the 1/sqrt(32) softmax scale folded into q.
// ---------------------------------------------------------------------------
__global__ __launch_bounds__(192) void norm_rope(
    const float* __restrict__ coords,
    const int*   __restrict__ seq,
    const float* __restrict__ qw,
    const float* __restrict__ kw,
    const float* __restrict__ freqs)
{
    const int t = threadIdx.x;
    const int tok = blockIdx.x;
    const int head = t >> 1, half = t & 1;
    const int g = head >> 3, h = head & 7;
    const int b = tok >> 9, n = tok & 511;

    const float pos = (float)seq[tok];
    const float cx = coords[tok * 3 + 0];
    const float cy = coords[tok * 3 + 1];
    const float cz = coords[tok * 3 + 2];

    const float th = (float)g * 0.52359877559829887f;
    const float cg = cosf(th), sg = sinf(th);
    const float r0 = cx * cg + cy * sg;
    const float r1 = cy * cg - cx * sg;
    const float r2 = cz;

    const size_t basei = (((size_t)b * 96 + head) * 512 + n) * 32 + half * 16;
    const float* qp = g_q + basei;
    const float* kp = g_k + basei;

    float qv[16], kv[16];
    #pragma unroll
    for (int e = 0; e < 4; e++) {
        float4 a = *(const float4*)(qp + e * 4);
        qv[e*4+0] = a.x; qv[e*4+1] = a.y; qv[e*4+2] = a.z; qv[e*4+3] = a.w;
        float4 c = *(const float4*)(kp + e * 4);
        kv[e*4+0] = c.x; kv[e*4+1] = c.y; kv[e*4+2] = c.z; kv[e*4+3] = c.w;
    }

    float sq = 0.f, sk = 0.f;
    #pragma unroll
    for (int e = 0; e < 16; e++) { sq += qv[e] * qv[e]; sk += kv[e] * kv[e]; }
    sq += __shfl_xor_sync(0xffffffffu, sq, 1);
    sk += __shfl_xor_sync(0xffffffffu, sk, 1);

    const float eps = 1.1920929e-07f;
    const float rq = rsqrtf(sq * (1.0f / 32.0f) + eps);
    const float rk = rsqrtf(sk * (1.0f / 32.0f) + eps);

    #pragma unroll
    for (int jj = 0; jj < 8; jj++) {
        const int j = half * 8 + jj;
        const float invf = (float)exp(-(double)j * 0.57564627324851148);
        const float* F = freqs + (h * 16 + j) * 3;
        const float phase = pos * invf + r0 * F[0] + r1 * F[1] + r2 * F[2];
        float sn, cs;
        sincosf(phase, &sn, &cs);

        float x1 = qv[2*jj]   * rq * qw[2*j];
        float x2 = qv[2*jj+1] * rq * qw[2*j+1];
        qv[2*jj]   = x1 * cs - x2 * sn;
        qv[2*jj+1] = x1 * sn + x2 * cs;

        float y1 = kv[2*jj]   * rk * kw[2*j];
        float y2 = kv[2*jj+1] * rk * kw[2*j+1];
        kv[2*jj]   = y1 * cs - y2 * sn;
        kv[2*jj+1] = y1 * sn + y2 * cs;
    }

    // fold softmax scale into q
    #pragma unroll
    for (int e = 0; e < 16; e++) qv[e] *= 0.17677669529663687f;

    uint32_t hq[8], lq[8], hk[8], lk[8];
    #pragma unroll
    for (int e = 0; e < 8; e++) {
        hq[e] = packbf(qv[2*e], qv[2*e+1]);
        lq[e] = packlo(qv[2*e], qv[2*e+1], hq[e]);
        hk[e] = packbf(kv[2*e], kv[2*e+1]);
        lk[e] = packlo(kv[2*e], kv[2*e+1], hk[e]);
    }
    *(uint4*)&g_qh[basei]     = make_uint4(hq[0], hq[1], hq[2], hq[3]);
    *(uint4*)&g_qh[basei + 8] = make_uint4(hq[4], hq[5], hq[6], hq[7]);
    *(uint4*)&g_ql[basei]     = make_uint4(lq[0], lq[1], lq[2], lq[3]);
    *(uint4*)&g_ql[basei + 8] = make_uint4(lq[4], lq[5], lq[6], lq[7]);
    *(uint4*)&g_kh[basei]     = make_uint4(hk[0], hk[1], hk[2], hk[3]);
    *(uint4*)&g_kh[basei + 8] = make_uint4(hk[4], hk[5], hk[6], hk[7]);
    *(uint4*)&g_kl[basei]     = make_uint4(lk[0], lk[1], lk[2], lk[3]);
    *(uint4*)&g_kl[basei + 8] = make_uint4(lk[4], lk[5], lk[6], lk[7]);
}

// ---------------------------------------------------------------------------
// Tensor-core attention. CTA = (qblock of 128 rows, head). 4 warps, each
// owns 32 q rows. 3-term hi/lo bf16 MMA for both QK^T and PV; fast_exp;
// no max-subtraction needed (|S| <= sqrt(32)). Output -> bf16 hi/lo g_att.
// ---------------------------------------------------------------------------
__global__ __launch_bounds__(128) void attn_mma()
{
    __shared__ __align__(128) char sm[32768];
    const uint32_t sb = smem_u32(sm);
    const int tid = threadIdx.x, wid = tid >> 5, lane = tid & 31;
    const int bh = blockIdx.y;
    const int row0 = blockIdx.x * 128;

    // ---- stage Q hi/lo (128 rows x 64B data in 128B padded rows) ----
    {
        const uint4* srch = (const uint4*)(g_qh + ((size_t)bh * 512 + row0) * 32);
        const uint4* srcl = (const uint4*)(g_ql + ((size_t)bh * 512 + row0) * 32);
        #pragma unroll
        for (int i = 0; i < 4; i++) {
            const int idx = tid + i * 128;          // 512 uint4
            const int r = idx >> 2, c = idx & 3;
            const uint32_t sw = SMEM_SWIZZLE_128B(r * 128 + c * 16);
            *(uint4*)(sm + sw)         = srch[idx];
            *(uint4*)(sm + 16384 + sw) = srcl[idx];
        }
    }
    __syncthreads();

    // persistent Q A-fragments: [mt][kc][4]
    uint32_t qh[2][2][4], ql[2][2][4];
    {
        const int ar = wid * 32 + (lane & 15);
        const int ac = (lane >> 4) * 16;
        #pragma unroll
        for (int mt = 0; mt < 2; mt++)
            #pragma unroll
            for (int kc = 0; kc < 2; kc++) {
                const uint32_t off = SMEM_SWIZZLE_128B((ar + mt * 16) * 128 + kc * 32 + ac);
                ldsm4(qh[mt][kc], sb + off);
                ldsm4(ql[mt][kc], sb + 16384 + off);
            }
    }

    float O[2][4][4] = {};
    float l[2][2] = {};

    const uint4* kh_g = (const uint4*)(g_kh + (size_t)bh * 512 * 32);
    const uint4* kl_g = (const uint4*)(g_kl + (size_t)bh * 512 * 32);
    const uint4* vh_g = (const uint4*)(g_vh + (size_t)bh * 512 * 32);
    const uint4* vl_g = (const uint4*)(g_vl + (size_t)bh * 512 * 32);

    for (int kb = 0; kb < 8; kb++) {
        __syncthreads();
        // K/V hi/lo tiles: 64 keys x 32 dims each (8KB padded per tile)
        #pragma unroll
        for (int i = 0; i < 2; i++) {
            const int idx = tid + i * 128;          // 256 uint4 per tile
            const int r = idx >> 2, c = idx & 3;
            const uint32_t sw = SMEM_SWIZZLE_128B(r * 128 + c * 16);
            const int gi = kb * 256 + idx;
            *(uint4*)(sm + 0     + sw) = kh_g[gi];
            *(uint4*)(sm + 8192  + sw) = kl_g[gi];
            *(uint4*)(sm + 16384 + sw) = vh_g[gi];
            *(uint4*)(sm + 24576 + sw) = vl_g[gi];
        }
        __syncthreads();

        // ---- S = (Qh+Ql)(Kh+Kl)^T, 3 terms ----
        float S[2][8][4] = {};
        #pragma unroll
        for (int kc = 0; kc < 2; kc++) {
            uint32_t kbh[4][4], kbl[4][4];
            const int br = ((lane >> 4) << 3) + (lane & 7);
            const int bc = kc * 32 + ((lane >> 3) & 1) * 16;
            #pragma unroll
            for (int pt = 0; pt < 4; pt++) {
                const uint32_t off = SMEM_SWIZZLE_128B((pt * 16 + br) * 128 + bc);
                ldsm4(kbh[pt], sb + 0 + off);
                ldsm4(kbl[pt], sb + 8192 + off);
            }
            #pragma unroll
            for (int mt = 0; mt < 2; mt++)
                #pragma unroll
                for (int pt = 0; pt < 4; pt++) {
                    mma16816(S[mt][2*pt+0], qh[mt][kc], kbh[pt][0], kbh[pt][1]);
                    mma16816(S[mt][2*pt+1], qh[mt][kc], kbh[pt][2], kbh[pt][3]);
                    mma16816(S[mt][2*pt+0], qh[mt][kc], kbl[pt][0], kbl[pt][1]);
                    mma16816(S[mt][2*pt+1], qh[mt][kc], kbl[pt][2], kbl[pt][3]);
                    mma16816(S[mt][2*pt+0], ql[mt][kc], kbh[pt][0], kbh[pt][1]);
                    mma16816(S[mt][2*pt+1], ql[mt][kc], kbh[pt][2], kbh[pt][3]);
                }
        }

        // ---- P = exp(S), row sums ----
        #pragma unroll
        for (int mt = 0; mt < 2; mt++)
            #pragma unroll
            for (int nt = 0; nt < 8; nt++) {
                S[mt][nt][0] = fast_exp(S[mt][nt][0]);
                S[mt][nt][1] = fast_exp(S[mt][nt][1]);
                S[mt][nt][2] = fast_exp(S[mt][nt][2]);
                S[mt][nt][3] = fast_exp(S[mt][nt][3]);
                l[mt][0] += S[mt][nt][0] + S[mt][nt][1];
                l[mt][1] += S[mt][nt][2] + S[mt][nt][3];
            }

        // ---- O += (Ph+Pl)(Vh+Vl), 3 terms; P refragmented in-register ----
        #pragma unroll
        for (int kc = 0; kc < 4; kc++) {
            uint32_t vbh[2][4], vbl[2][4];
            const int vr = kc * 16 + (lane & 15);
            const int vc = (lane >> 4) * 16;
            #pragma unroll
            for (int dh = 0; dh < 2; dh++) {
                const uint32_t off = SMEM_SWIZZLE_128B(vr * 128 + dh * 32 + vc);
                ldsm4t(vbh[dh], sb + 16384 + off);
                ldsm4t(vbl[dh], sb + 24576 + off);
            }
            #pragma unroll
            for (int mt = 0; mt < 2; mt++) {
                const float* s0 = S[mt][2*kc];
                const float* s1 = S[mt][2*kc+1];
                uint32_t ph[4], pl[4];
                ph[0] = packbf(s0[0], s0[1]); pl[0] = packlo(s0[0], s0[1], ph[0]);
                ph[1] = packbf(s0[2], s0[3]); pl[1] = packlo(s0[2], s0[3], ph[1]);
                ph[2] = packbf(s1[0], s1[1]); pl[2] = packlo(s1[0], s1[1], ph[2]);
                ph[3] = packbf(s1[2], s1[3]); pl[3] = packlo(s1[2], s1[3], ph[3]);
                #pragma unroll
                for (int nt = 0; nt < 4; nt++) {
                    const int dh = nt >> 1, hf = (nt & 1) * 2;
                    mma16816(O[mt][nt], ph, vbh[dh][hf], vbh[dh][hf+1]);
                    mma16816(O[mt][nt], ph, vbl[dh][hf], vbl[dh][hf+1]);
                    mma16816(O[mt][nt], pl, vbh[dh][hf], vbh[dh][hf+1]);
                }
            }
        }
    }

    // ---- normalize and write bf16 hi/lo ----
    #pragma unroll
    for (int mt = 0; mt < 2; mt++)
        #pragma unroll
        for (int j = 0; j < 2; j++) {
            l[mt][j] += __shfl_xor_sync(0xffffffffu, l[mt][j], 1);
            l[mt][j] += __shfl_xor_sync(0xffffffffu, l[mt][j], 2);
        }
    const float inv[2][2] = { {1.f/l[0][0], 1.f/l[0][1]}, {1.f/l[1][0], 1.f/l[1][1]} };

    const int b = bh / 96, head = bh % 96;
    const int cb = (head >> 3) * 256 + (head & 7) * 32;
    #pragma unroll
    for (int mt = 0; mt < 2; mt++) {
        const int r = row0 + wid * 32 + mt * 16 + (lane >> 2);
        const size_t t0 = ((size_t)(b * 512 + r)) * 3072 + cb;
        const size_t t1 = ((size_t)(b * 512 + r + 8)) * 3072 + cb;
        #pragma unroll
        for (int nt = 0; nt < 4; nt++) {
            const int d = nt * 8 + (lane & 3) * 2;
            const float o0 = O[mt][nt][0] * inv[mt][0];
            const float o1 = O[mt][nt][1] * inv[mt][0];
            const float o2 = O[mt][nt][2] * inv[mt][1];
            const float o3 = O[mt][nt][3] * inv[mt][1];
            const uint32_t h01 = packbf(o0, o1);
            const uint32_t h23 = packbf(o2, o3);
            *(uint32_t*)&g_att_hi[t0 + d] = h01;
            *(uint32_t*)&g_att_lo[t0 + d] = packlo(o0, o1, h01);
            *(uint32_t*)&g_att_hi[t1 + d] = h23;
            *(uint32_t*)&g_att_lo[t1 + d] = packlo(o2, o3, h23);
        }
    }
}

// ---------------------------------------------------------------------------
// Output projection: C[1024 x 768] = att[1024 x 3072] * Wo' (circulant).
// ---------------------------------------------------------------------------
__global__ __launch_bounds__(256) void out_mma(float* __restrict__ out)
{
    extern __shared__ __align__(16) char smem[];
    const uint32_t sb = smem_u32(smem);
    const int tid = threadIdx.x, wid = tid >> 5, lane = tid & 31;
    const int wm = wid & 3, wn = wid >> 2;
    const int m0 = blockIdx.y * 128;
    const int J0 = blockIdx.x * 128;

    float acc[2][8][4] = {};

    const int a_r = wm * 32 + (lane & 15);
    const int a_c2 = ((lane >> 4) << 3) * 2;
    const int b_r = wn * 64 + ((lane >> 4) << 3) + (lane & 7);
    const int b_c2 = (((lane >> 3) & 1) << 3) * 2;

    for (int ch = 0; ch < 48; ch++) {
        __syncthreads();
        const int gsrc = ch >> 2;
        const int i0 = (ch & 3) * 64;

        #pragma unroll
        for (int c = 0; c < 4; c++) {
            const int chunk = tid + c * 256;
            const int row = chunk >> 3, c8 = chunk & 7;
            const uint32_t sw = SMEM_SWIZZLE_128B(row * 128 + c8 * 16);
            const size_t aoff = (size_t)(m0 + row) * KOUT + ch * 64 + c8 * 8;
            const int Jrow = J0 + row;
            const int g_out = Jrow >> 6, o = Jrow & 63;
            int gg = gsrc - g_out; if (gg < 0) gg += 12;
            const size_t boff = (size_t)(gg * 64 + o) * 256 + i0 + c8 * 8;
            *(uint4*)(smem + T_AH + sw) = *(const uint4*)(g_att_hi + aoff);
            *(uint4*)(smem + T_AL + sw) = *(const uint4*)(g_att_lo + aoff);
            *(uint4*)(smem + T_BH + sw) = *(const uint4*)(g_wo_hi + boff);
            *(uint4*)(smem + T_BL + sw) = *(const uint4*)(g_wo_lo + boff);
        }
        __syncthreads();

        #pragma unroll
        for (int ks = 0; ks < 4; ks++) {
            const int k0b = ks * 32;
            uint32_t ah[2][4], al[2][4], bh[4][4], bl[4][4];
            #pragma unroll
            for (int mt = 0; mt < 2; mt++) {
                const uint32_t off = SMEM_SWIZZLE_128B((a_r + mt * 16) * 128 + k0b + a_c2);
                ldsm4(ah[mt], sb + T_AH + off);
                ldsm4(al[mt], sb + T_AL + off);
            }
            #pragma unroll
            for (int pt = 0; pt < 4; pt++) {
                const uint32_t off = SMEM_SWIZZLE_128B((b_r + pt * 16) * 128 + k0b + b_c2);
                ldsm4(bh[pt], sb + T_BH + off);
                ldsm4(bl[pt], sb + T_BL + off);
            }
            #pragma unroll
            for (int mt = 0; mt < 2; mt++)
                #pragma unroll
                for (int pt = 0; pt < 4; pt++) {
                    mma16816(acc[mt][2*pt+0], ah[mt], bh[pt][0], bh[pt][1]);
                    mma16816(acc[mt][2*pt+1], ah[mt], bh[pt][2], bh[pt][3]);
                    mma16816(acc[mt][2*pt+0], ah[mt], bl[pt][0], bl[pt][1]);
                    mma16816(acc[mt][2*pt+1], ah[mt], bl[pt][2], bl[pt][3]);
                    mma16816(acc[mt][2*pt+0], al[mt], bh[pt][0], bh[pt][1]);
                    mma16816(acc[mt][2*pt+1], al[mt], bh[pt][2], bh[pt][3]);
                }
        }
    }

    #pragma unroll
    for (int mt = 0; mt < 2; mt++) {
        const int r = m0 + wm * 32 + mt * 16 + (lane >> 2);
        #pragma unroll
        for (int nt = 0; nt < 8; nt++) {
            const int J = J0 + wn * 64 + nt * 8 + (lane & 3) * 2;
            *(float2*)(out + (size_t)r * NOUT + J) =
                make_float2(acc[mt][nt][0], acc[mt][nt][1]);
            *(float2*)(out + (size_t)(r + 8) * NOUT + J) =
                make_float2(acc[mt][nt][2], acc[mt][nt][3]);
        }
    }
}

// ---------------------------------------------------------------------------
extern "C" void kernel_launch(void* const* d_in, const int* in_sizes, int n_in,
                              void* d_out, int out_size)
{
    (void)in_sizes; (void)n_in; (void)out_size;
    const float* feat   = (const float*)d_in[0];
    const float* coords = (const float*)d_in[1];
    const float* Wq     = (const float*)d_in[2];
    const float* Wk     = (const float*)d_in[3];
    const float* Wv     = (const float*)d_in[4];
    const float* Wo     = (const float*)d_in[5];
    const float* qw     = (const float*)d_in[6];
    const float* kw     = (const float*)d_in[7];
    const float* freqs  = (const float*)d_in[8];
    const int*   seq    = (const int*)d_in[9];
    float* out = (float*)d_out;

    cudaFuncSetAttribute(qkv_mma, cudaFuncAttributeMaxDynamicSharedMemorySize, MMA_SMEM_BYTES);
    cudaFuncSetAttribute(out_mma, cudaFuncAttributeMaxDynamicSharedMemorySize, MMA_SMEM_BYTES);

    prep_inputs<<<6144, 256>>>(feat, Wq, Wk, Wv, Wo);
    qkv_mma<<<dim3(72, 8), 256, MMA_SMEM_BYTES>>>();
    norm_rope<<<TOK, 192>>>(coords, seq, qw, kw, freqs);
    attn_mma<<<dim3(4, Bc * NHEAD), 128>>>();
    out_mma<<<dim3(6, 8), 256, MMA_SMEM_BYTES>>>(out);
}